// round 16
// baseline (speedup 1.0000x reference)
#include <cuda_runtime.h>
#include <cuda_bf16.h>
#include <cstdint>

#define EPSF 1e-8f
#define NKEY 100000
#define NBLK 1563   // ceil(100000/64)

#define QSCALE (127.0f / 6.0f)
#define QC2 ((6.0f / 127.0f) * (6.0f / 127.0f))
#define TH_COS 0.12f

// ---------------- scratch (device globals; no allocs allowed) ----------------
__device__ __align__(16) float          g_qrelu[256 * 512];
__device__ __align__(16) char           g_q8[256 * 512];     // int8 queries
__device__ __align__(16) float          g_qn[256];
__device__ __align__(16) int            g_topk[256 * 32];
__device__ __align__(16) float          g_hq[256 * 256];
__device__ __align__(16) float          g_M[8192 * 256];
__device__ __align__(16) int            g_cand_cnt[256];
__device__ __align__(16) int            g_cand_list[256 * 1024];
__device__ __align__(16) float          g_cand_simf[256 * 1024];

#define CP_ASYNC16(dst, src) \
    asm volatile("cp.async.ca.shared.global [%0], [%1], 16;\n" :: "r"(dst), "l"(src))
#define CP_COMMIT() asm volatile("cp.async.commit_group;\n")
#define CP_WAIT0()  asm volatile("cp.async.wait_group 0;\n")
#define CP_WAIT1()  asm volatile("cp.async.wait_group 1;\n")

__device__ __forceinline__ uint32_t smem_u32(const void* p) {
    uint32_t a;
    asm("{ .reg .u64 t; cvta.to.shared.u64 t, %1; cvt.u32.u64 %0, t; }" : "=r"(a) : "l"(p));
    return a;
}

// pack 4 s32 -> 4 saturated s8 bytes (b0=v0..b3=v3)
__device__ __forceinline__ uint32_t pack_s8x4(int v0, int v1, int v2, int v3) {
    uint32_t t1, w;
    asm("cvt.pack.sat.s8.s32.b32 %0, %1, %2, 0;" : "=r"(t1) : "r"(v3), "r"(v2));
    asm("cvt.pack.sat.s8.s32.b32 %0, %1, %2, %3;" : "=r"(w) : "r"(v1), "r"(v0), "r"(t1));
    return w;
}

__device__ __forceinline__ void cand_push(int m, int gn, float v) {
    if (v >= TH_COS) {
        int p = atomicAdd(&g_cand_cnt[m], 1);
        if (p < 1024) g_cand_list[m * 1024 + p] = gn;
    }
}

// ---------------- dummy (aligns ncu capture slot) ----------------
__global__ void k_nop() {}

// ---------------- K1: relu(q), int8 copy, row norms, zero cand counters ----------------
__global__ void k1_prep(const float* __restrict__ qf) {
    const int b = blockIdx.x, t = threadIdx.x;
    __shared__ float red[8];
    float s = 0.f;
#pragma unroll
    for (int i = 0; i < 2; i++) {
        int d = t + i * 256;
        float v = fmaxf(qf[b * 512 + d], 0.f);
        g_qrelu[b * 512 + d] = v;
        int vi = __float2int_rn(v * QSCALE);
        vi = max(-127, min(127, vi));
        g_q8[b * 512 + d] = (char)vi;
        s += v * v;
    }
    for (int o = 16; o; o >>= 1) s += __shfl_xor_sync(0xffffffffu, s, o);
    if ((t & 31) == 0) red[t >> 5] = s;
    __syncthreads();
    if (t == 0) {
        float tot = 0.f;
        for (int i = 0; i < 8; i++) tot += red[i];
        g_qn[b] = sqrtf(tot);
        g_cand_cnt[b] = 0;
    }
}

// ---------------- K2: int8 sim GEMM, cp.async-staged keys; fused select ----------------
// smem: As8 2x20480 | Bs8 2x5120 | Bf32 2x16384 | qn 1024 | kn 256  = 85248 B
// Bf row stride: 256 B (64 fp32 per key row, 4 threads x 64 B)
__global__ void __launch_bounds__(256) k2_sim(const float* __restrict__ keys) {
    extern __shared__ __align__(16) char dsm[];
    char*  As8 = dsm;
    char*  Bs8 = dsm + 40960;
    char*  Bf  = dsm + 51200;              // fp32 staging (bytes)
    float* qn_s = (float*)(dsm + 83968);
    float* kn_s = qn_s + 256;

    const int t = threadIdx.x;
    const int n0 = blockIdx.x * 64;
    qn_s[t] = g_qn[t];

    int acc[4][4][4];
#pragma unroll
    for (int a = 0; a < 4; a++)
#pragma unroll
        for (int b = 0; b < 4; b++)
#pragma unroll
            for (int c = 0; c < 4; c++) acc[a][b][c] = 0;

    float ssq = 0.f;
    const int lane = t & 31, warp = t >> 5;
    const int wm = warp >> 1, wn = warp & 1;
    const int rb = t >> 2, cq = t & 3;      // B: 4 threads/row, 64B each
    const bool rowok = (n0 + rb) < NKEY;
    const float* krow = keys + (size_t)(n0 + rb) * 512 + cq * 16;

    const uint32_t a_sm = smem_u32(As8);
    const uint32_t bf_sm = smem_u32(Bf);

    // convert one thread's 64B of Bf32(stage st) -> Bs8(stage st); zero if !rowok
    auto convertB = [&](int st) {
        uint4 w;
        uint32_t* wp = (uint32_t*)&w;
        if (rowok) {
            const float4* src =
                reinterpret_cast<const float4*>(Bf + st * 16384 + rb * 256 + cq * 64);
#pragma unroll
            for (int j = 0; j < 4; j++) {
                float4 q4 = src[j];
                ssq += q4.x * q4.x + q4.y * q4.y + q4.z * q4.z + q4.w * q4.w;
                wp[j] = pack_s8x4(__float2int_rn(q4.x * QSCALE), __float2int_rn(q4.y * QSCALE),
                                  __float2int_rn(q4.z * QSCALE), __float2int_rn(q4.w * QSCALE));
            }
        } else {
            w = make_uint4(0u, 0u, 0u, 0u);
        }
        *reinterpret_cast<uint4*>(Bs8 + st * 5120 + rb * 80 + cq * 16) = w;
    };

    // --- prologue: stage 0 (A s8 + B fp32) via cp.async ---
#pragma unroll
    for (int i = 0; i < 4; i++) {
        int r = rb + 64 * i;
        CP_ASYNC16(a_sm + (uint32_t)(r * 80 + cq * 16), (const void*)&g_q8[r * 512 + cq * 16]);
    }
    if (rowok) {
#pragma unroll
        for (int q = 0; q < 4; q++)
            CP_ASYNC16(bf_sm + (uint32_t)(rb * 256 + cq * 64 + q * 16),
                       (const void*)(krow + q * 4));
    }
    CP_COMMIT();
    CP_WAIT0();
    convertB(0);

    for (int s = 0; s < 8; s++) {
        const int cur = s & 1, nxt = cur ^ 1;
        const bool hn = s < 7;
        if (hn) {
            const int k0n = (s + 1) * 64;
#pragma unroll
            for (int i = 0; i < 4; i++) {
                int r = rb + 64 * i;
                CP_ASYNC16(a_sm + (uint32_t)(nxt * 20480 + r * 80 + cq * 16),
                           (const void*)&g_q8[r * 512 + k0n + cq * 16]);
            }
            if (rowok) {
#pragma unroll
                for (int q = 0; q < 4; q++)
                    CP_ASYNC16(bf_sm + (uint32_t)(nxt * 16384 + rb * 256 + cq * 64 + q * 16),
                               (const void*)(krow + k0n + q * 4));
            }
            CP_COMMIT();
        }
        __syncthreads();                    // Bs8(cur) + As8(cur) visible to all

        const uint32_t ab = a_sm + cur * 20480;
        const uint32_t bb = smem_u32(Bs8) + cur * 5120;
#pragma unroll
        for (int ks = 0; ks < 2; ks++) {
            const int kb = ks * 32;
            uint32_t af[4][4];
#pragma unroll
            for (int mi = 0; mi < 4; mi++) {
                int row = wm * 64 + mi * 16 + (lane & 15);
                uint32_t addr = ab + (uint32_t)(row * 80 + kb + ((lane >> 4) << 4));
                asm volatile("ldmatrix.sync.aligned.m8n8.x4.shared.b16 {%0,%1,%2,%3}, [%4];"
                             : "=r"(af[mi][0]), "=r"(af[mi][1]), "=r"(af[mi][2]), "=r"(af[mi][3])
                             : "r"(addr));
            }
            uint32_t bfr[4][2];
#pragma unroll
            for (int p = 0; p < 2; p++) {
                int g = lane >> 3, r = lane & 7;
                int nrow = wn * 32 + p * 16 + ((g >> 1) << 3) + r;
                uint32_t addr = bb + (uint32_t)(nrow * 80 + kb + ((g & 1) << 4));
                uint32_t r0, r1, r2, r3;
                asm volatile("ldmatrix.sync.aligned.m8n8.x4.shared.b16 {%0,%1,%2,%3}, [%4];"
                             : "=r"(r0), "=r"(r1), "=r"(r2), "=r"(r3) : "r"(addr));
                bfr[p * 2][0] = r0;     bfr[p * 2][1] = r1;
                bfr[p * 2 + 1][0] = r2; bfr[p * 2 + 1][1] = r3;
            }
#pragma unroll
            for (int mi = 0; mi < 4; mi++)
#pragma unroll
                for (int ni = 0; ni < 4; ni++)
                    asm volatile(
                        "mma.sync.aligned.m16n8k32.row.col.s32.s8.s8.s32 "
                        "{%0,%1,%2,%3}, {%4,%5,%6,%7}, {%8,%9}, {%0,%1,%2,%3};"
                        : "+r"(acc[mi][ni][0]), "+r"(acc[mi][ni][1]),
                          "+r"(acc[mi][ni][2]), "+r"(acc[mi][ni][3])
                        : "r"(af[mi][0]), "r"(af[mi][1]), "r"(af[mi][2]), "r"(af[mi][3]),
                          "r"(bfr[ni][0]), "r"(bfr[ni][1]));
        }

        if (hn) {
            CP_WAIT0();                     // stage s+1 data landed (own-thread bytes)
            convertB(nxt);                  // overlapped past mma issue; own data only
        }
        __syncthreads();                    // all reads of stage cur done before reuse
    }

    ssq += __shfl_xor_sync(0xffffffffu, ssq, 1);
    ssq += __shfl_xor_sync(0xffffffffu, ssq, 2);
    if (cq == 0) kn_s[rb] = sqrtf(ssq);
    __syncthreads();

    // epilogue: cosine scaling + fused candidate push (no sim-matrix store)
#pragma unroll
    for (int mi = 0; mi < 4; mi++) {
        int m = wm * 64 + mi * 16 + (lane >> 2);
        float qn0 = qn_s[m], qn1 = qn_s[m + 8];
#pragma unroll
        for (int ni = 0; ni < 4; ni++) {
            int nl = wn * 32 + ni * 8 + ((lane & 3) << 1);
            int gn = n0 + nl;
            if (gn < NKEY) {
                float kn0 = kn_s[nl], kn1 = kn_s[nl + 1];
                cand_push(m,     gn,     (float)acc[mi][ni][0] * (QC2 / fmaxf(qn0 * kn0, EPSF)));
                cand_push(m,     gn + 1, (float)acc[mi][ni][1] * (QC2 / fmaxf(qn0 * kn1, EPSF)));
                cand_push(m + 8, gn,     (float)acc[mi][ni][2] * (QC2 / fmaxf(qn1 * kn0, EPSF)));
                cand_push(m + 8, gn + 1, (float)acc[mi][ni][3] * (QC2 / fmaxf(qn1 * kn1, EPSF)));
            }
        }
    }
}

// ---------------- K3a: rescore candidates (4 blocks per query, disjoint strides) ---------
__global__ void __launch_bounds__(256) k3_rescore(const float* __restrict__ keys) {
    const int b = blockIdx.x >> 2, j = blockIdx.x & 3;
    const int t = threadIdx.x;
    __shared__ float q_s[512];
    q_s[t] = g_qrelu[b * 512 + t];
    q_s[t + 256] = g_qrelu[b * 512 + 256 + t];
    __syncthreads();

    const int cnt = g_cand_cnt[b];
    if (cnt < 48 || cnt > 1024) return;          // fallback handled in k3b

    const int lane = t & 31, warp = t >> 5;
    const float qn = g_qn[b];
    for (int c = j * 8 + warp; c < cnt; c += 32) {
        const float* kp = keys + (size_t)g_cand_list[b * 1024 + c] * 512;
        float4 kv[4], qv[4];
#pragma unroll
        for (int i = 0; i < 4; i++) {
            kv[i] = *reinterpret_cast<const float4*>(kp + i * 128 + lane * 4);
            qv[i] = *reinterpret_cast<const float4*>(&q_s[i * 128 + lane * 4]);
        }
        float d0 = 0.f, d1 = 0.f, d2 = 0.f, d3 = 0.f;
        float s0 = 0.f, s1 = 0.f, s2 = 0.f, s3 = 0.f;
#pragma unroll
        for (int i = 0; i < 4; i++) {
            d0 += qv[i].x * kv[i].x;  s0 += kv[i].x * kv[i].x;
            d1 += qv[i].y * kv[i].y;  s1 += kv[i].y * kv[i].y;
            d2 += qv[i].z * kv[i].z;  s2 += kv[i].z * kv[i].z;
            d3 += qv[i].w * kv[i].w;  s3 += kv[i].w * kv[i].w;
        }
        float dot = (d0 + d1) + (d2 + d3);
        float ksq = (s0 + s1) + (s2 + s3);
        for (int o = 16; o; o >>= 1) {
            dot += __shfl_xor_sync(0xffffffffu, dot, o);
            ksq += __shfl_xor_sync(0xffffffffu, ksq, o);
        }
        if (lane == 0)
            g_cand_simf[b * 1024 + c] = dot / fmaxf(qn * sqrtf(ksq), EPSF);
    }
}

// ---------------- K3b: exact top-32 (fast: from rescored list; fallback: exact argmax) ---
__global__ void __launch_bounds__(512) k3b_topk(const float* __restrict__ keys) {
    const int b = blockIdx.x, t = threadIdx.x;
    const int lane = t & 31, warp = t >> 5;
    __shared__ int   cand_idx[1024];
    __shared__ float cand_sim[1024];
    __shared__ float q_s[512];
    __shared__ float wb_v[16];
    __shared__ int   wb_i[16];
    __shared__ int   sel[32];

    const int cnt_raw = g_cand_cnt[b];

    if (cnt_raw >= 48 && cnt_raw <= 1024) {
        const int cnt = cnt_raw;
        for (int i = t; i < cnt; i += 512) {
            cand_idx[i] = g_cand_list[b * 1024 + i];
            cand_sim[i] = g_cand_simf[b * 1024 + i];
        }
        __syncthreads();
        if (warp == 0) {
            for (int r = 0; r < 32; r++) {
                float best = -1e30f; int bkey = 0x7fffffff, bslot = -1;
                for (int c = lane; c < cnt; c += 32) {
                    float v = cand_sim[c]; int ki = cand_idx[c];
                    if (v > best || (v == best && ki < bkey)) { best = v; bkey = ki; bslot = c; }
                }
                for (int o = 16; o; o >>= 1) {
                    float ov = __shfl_xor_sync(0xffffffffu, best, o);
                    int   ok = __shfl_xor_sync(0xffffffffu, bkey, o);
                    int   os = __shfl_xor_sync(0xffffffffu, bslot, o);
                    if (ov > best || (ov == best && ok < bkey)) { best = ov; bkey = ok; bslot = os; }
                }
                if (lane == 0) {
                    g_topk[b * 32 + r] = bkey;
                    cand_sim[bslot] = -2e30f;
                }
                __syncwarp();
            }
        }
        return;
    }

    // ---- robust fallback (dead code for this input distribution): exact 32-pass argmax ----
    q_s[t] = g_qrelu[b * 512 + t];
    __syncthreads();
    const float qn = g_qn[b];
    for (int r = 0; r < 32; r++) {
        float best = -1e30f; int bkey = 0x7fffffff;
        for (int k = warp; k < NKEY; k += 16) {
            bool taken = false;
            for (int u = 0; u < r; u++) taken |= (sel[u] == k);
            if (taken) continue;
            const float* kp = keys + (size_t)k * 512;
            float dot = 0.f, ksq = 0.f;
#pragma unroll
            for (int i = 0; i < 4; i++) {
                float4 kv = *reinterpret_cast<const float4*>(kp + i * 128 + lane * 4);
                float4 qv = *reinterpret_cast<const float4*>(&q_s[i * 128 + lane * 4]);
                dot += qv.x * kv.x + qv.y * kv.y + qv.z * kv.z + qv.w * kv.w;
                ksq += kv.x * kv.x + kv.y * kv.y + kv.z * kv.z + kv.w * kv.w;
            }
            for (int o = 16; o; o >>= 1) {
                dot += __shfl_xor_sync(0xffffffffu, dot, o);
                ksq += __shfl_xor_sync(0xffffffffu, ksq, o);
            }
            float v = dot / fmaxf(qn * sqrtf(ksq), EPSF);
            if (v > best || (v == best && k < bkey)) { best = v; bkey = k; }
        }
        if (lane == 0) { wb_v[warp] = best; wb_i[warp] = bkey; }
        __syncthreads();
        if (t == 0) {
            float bv = -1e30f; int bi = 0x7fffffff;
            for (int w = 0; w < 16; w++) {
                if (wb_v[w] > bv || (wb_v[w] == bv && wb_i[w] < bi)) { bv = wb_v[w]; bi = wb_i[w]; }
            }
            sel[r] = bi;
            g_topk[b * 32 + r] = bi;
        }
        __syncthreads();
    }
}

// ---------------- K4: tf32 GEMM, cp.async double-buffered, dual-task grid ----------------
__global__ void __launch_bounds__(256) k_tf32(const float* __restrict__ A,
                                              const float* __restrict__ W,
                                              const int* __restrict__ idx,
                                              const float* __restrict__ b1,
                                              const float* __restrict__ b2,
                                              float* __restrict__ C,
                                              const float* __restrict__ A2,
                                              const float* __restrict__ W2,
                                              const float* __restrict__ b2a,
                                              const float* __restrict__ b2b,
                                              float* __restrict__ C2) {
    if (blockIdx.z == 1) {
        if (blockIdx.x >= 2) return;     // small task: M=256 -> 2 M-blocks
        A = A2; W = W2; idx = nullptr; b1 = b2a; b2 = b2b; C = C2;
    }
    extern __shared__ __align__(16) char sm2[];
    uint32_t* AsU = (uint32_t*)sm2;                       // 2 stages x 128x36
    uint32_t* BsU = (uint32_t*)(sm2 + 2 * 128 * 36 * 4);  // 2 stages x 32x72
    const uint32_t as32 = smem_u32(AsU);
    const uint32_t bs32 = smem_u32(BsU);

    const int t = threadIdx.x;
    const int lane = t & 31, warp = t >> 5;
    const int wm = (warp >> 1) * 32, wn = (warp & 1) * 32;
    const int m0 = blockIdx.x * 128, n0 = blockIdx.y * 64;

    float acc[2][4][4];
#pragma unroll
    for (int i = 0; i < 2; i++)
#pragma unroll
        for (int j = 0; j < 4; j++)
#pragma unroll
            for (int k = 0; k < 4; k++) acc[i][j][k] = 0.f;

    const int alrow = t >> 1;
    const int acol0 = (t & 1) * 16;
    const float* arow = (idx ? (A + (size_t)idx[m0 + alrow] * 512)
                             : (A + (size_t)(m0 + alrow) * 512)) + acol0;
    const int wr = t >> 3;
    const int wc = (t & 7) * 8;
    const float* wrow = W + (size_t)wr * 256 + n0 + wc;

    // issue stage 0 (k0 = 0)
#pragma unroll
    for (int q = 0; q < 4; q++)
        CP_ASYNC16(as32 + (uint32_t)((alrow * 36 + acol0 + q * 4) * 4),
                   (const void*)(arow + q * 4));
#pragma unroll
    for (int q = 0; q < 2; q++)
        CP_ASYNC16(bs32 + (uint32_t)((wr * 72 + wc + q * 4) * 4),
                   (const void*)(wrow + q * 4));
    CP_COMMIT();

    for (int it = 0; it < 16; it++) {
        const int cur = it & 1, nxt = cur ^ 1;
        const bool hn = it < 15;
        if (hn) {
            const int kn = (it + 1) * 32;
#pragma unroll
            for (int q = 0; q < 4; q++)
                CP_ASYNC16(as32 + (uint32_t)(((nxt * 128 + alrow) * 36 + acol0 + q * 4) * 4),
                           (const void*)(arow + kn + q * 4));
#pragma unroll
            for (int q = 0; q < 2; q++)
                CP_ASYNC16(bs32 + (uint32_t)(((nxt * 32 + wr) * 72 + wc + q * 4) * 4),
                           (const void*)(wrow + (size_t)kn * 256 + q * 4));
            CP_COMMIT();
            CP_WAIT1();
        } else {
            CP_WAIT0();
        }
        __syncthreads();

        const uint32_t* Ac = AsU + cur * 128 * 36;
        const uint32_t* Bc = BsU + cur * 32 * 72;
#pragma unroll
        for (int ks = 0; ks < 4; ks++) {
            const int kc = ks * 8;
            uint32_t a[2][4];
#pragma unroll
            for (int mi = 0; mi < 2; mi++) {
                int r0 = wm + mi * 16 + (lane >> 2);
                a[mi][0] = Ac[r0 * 36 + kc + (lane & 3)];
                a[mi][1] = Ac[(r0 + 8) * 36 + kc + (lane & 3)];
                a[mi][2] = Ac[r0 * 36 + kc + (lane & 3) + 4];
                a[mi][3] = Ac[(r0 + 8) * 36 + kc + (lane & 3) + 4];
            }
            uint32_t bb[4][2];
#pragma unroll
            for (int ni = 0; ni < 4; ni++) {
                int nc = wn + ni * 8 + (lane >> 2);
                bb[ni][0] = Bc[(kc + (lane & 3)) * 72 + nc];
                bb[ni][1] = Bc[(kc + (lane & 3) + 4) * 72 + nc];
            }
#pragma unroll
            for (int mi = 0; mi < 2; mi++)
#pragma unroll
                for (int ni = 0; ni < 4; ni++)
                    asm volatile(
                        "mma.sync.aligned.m16n8k8.row.col.f32.tf32.tf32.f32 "
                        "{%0,%1,%2,%3}, {%4,%5,%6,%7}, {%8,%9}, {%0,%1,%2,%3};"
                        : "+f"(acc[mi][ni][0]), "+f"(acc[mi][ni][1]),
                          "+f"(acc[mi][ni][2]), "+f"(acc[mi][ni][3])
                        : "r"(a[mi][0]), "r"(a[mi][1]), "r"(a[mi][2]), "r"(a[mi][3]),
                          "r"(bb[ni][0]), "r"(bb[ni][1]));
        }
        __syncthreads();
    }

#pragma unroll
    for (int mi = 0; mi < 2; mi++) {
        int r0 = m0 + wm + mi * 16 + (lane >> 2);
#pragma unroll
        for (int ni = 0; ni < 4; ni++) {
            int c0 = n0 + wn + ni * 8 + (lane & 3) * 2;
            float add0 = (b1 ? b1[c0] : 0.f) + (b2 ? b2[c0] : 0.f);
            float add1 = (b1 ? b1[c0 + 1] : 0.f) + (b2 ? b2[c0 + 1] : 0.f);
            C[(size_t)r0 * 256 + c0]           = acc[mi][ni][0] + add0;
            C[(size_t)r0 * 256 + c0 + 1]       = acc[mi][ni][1] + add1;
            C[(size_t)(r0 + 8) * 256 + c0]     = acc[mi][ni][2] + add0;
            C[(size_t)(r0 + 8) * 256 + c0 + 1] = acc[mi][ni][3] + add1;
        }
    }
}

// ---------------- K5: scores -> softmax -> attended -> classifier (coalesced) ------------
__global__ void k5_final(const float* __restrict__ keys, const float* __restrict__ Ws,
                         const float* __restrict__ bs, const float* __restrict__ Wc,
                         const float* __restrict__ bc, float* __restrict__ out) {
    const int b = blockIdx.x, t = threadIdx.x, lane = t & 31, warp = t >> 5;
    __shared__ float hq_s[256], sc_s[32], w_s[32], merged[1024];
    __shared__ float part[8][128];
    __shared__ int idx_s[32];
    hq_s[t] = g_hq[b * 256 + t];
    if (t < 32) idx_s[t] = g_topk[b * 32 + t];
    merged[t] = g_qrelu[b * 512 + t];
    merged[256 + t] = g_qrelu[b * 512 + 256 + t];
    __syncthreads();

    for (int k = warp; k < 32; k += 8) {
        const float* Mrow = &g_M[(size_t)(b * 32 + k) * 256];
        float s = 0.f;
        for (int a = lane; a < 256; a += 32) s += tanhf(hq_s[a] + Mrow[a]) * Ws[a];
        for (int o = 16; o; o >>= 1) s += __shfl_xor_sync(0xffffffffu, s, o);
        if (lane == 0) sc_s[k] = s + bs[0];
    }
    __syncthreads();
    if (t < 32) {
        float v = sc_s[t];
        float m = v;
        for (int o = 16; o; o >>= 1) m = fmaxf(m, __shfl_xor_sync(0xffffffffu, m, o));
        float e = expf(v - m);
        float sm = e;
        for (int o = 16; o; o >>= 1) sm += __shfl_xor_sync(0xffffffffu, sm, o);
        w_s[t] = e / sm;
    }
    __syncthreads();
    for (int d = t; d < 512; d += 256) {
        float a = 0.f;
#pragma unroll 8
        for (int k = 0; k < 32; k++) a += w_s[k] * keys[(size_t)idx_s[k] * 512 + d];
        merged[512 + d] = a;
    }
    __syncthreads();

    // classifier: lanes map to output columns (coalesced Wc reads), warps split j
    {
        float a0 = 0.f, a1 = 0.f, a2 = 0.f, a3 = 0.f;
        const int j0 = warp * 128;
        for (int j = j0; j < j0 + 128; j++) {
            float mv = merged[j];
            const float* wr = Wc + (size_t)j * 100;
            a0 += mv * wr[lane];
            a1 += mv * wr[lane + 32];
            a2 += mv * wr[lane + 64];
            if (lane < 4) a3 += mv * wr[lane + 96];
        }
        part[warp][lane] = a0;
        part[warp][lane + 32] = a1;
        part[warp][lane + 64] = a2;
        if (lane < 4) part[warp][lane + 96] = a3;
    }
    __syncthreads();
    if (t < 100) {
        float s = bc[t];
#pragma unroll
        for (int w = 0; w < 8; w++) s += part[w][t];
        out[b * 100 + t] = s;
    }
}

// ---------------- launch ----------------
extern "C" void kernel_launch(void* const* d_in, const int* in_sizes, int n_in,
                              void* d_out, int out_size) {
    const float* qf   = (const float*)d_in[0];
    const float* keys = (const float*)d_in[1];
    const float* Wq   = (const float*)d_in[2];
    const float* bq   = (const float*)d_in[3];
    const float* Wm   = (const float*)d_in[4];
    const float* bm   = (const float*)d_in[5];
    const float* Ws   = (const float*)d_in[6];
    const float* bs   = (const float*)d_in[7];
    const float* Wc   = (const float*)d_in[8];
    const float* bc   = (const float*)d_in[9];
    float* out = (float*)d_out;

    int* topk_ptr = nullptr;
    float* M_ptr = nullptr; float* hq_ptr = nullptr; float* qrelu_ptr = nullptr;
    cudaGetSymbolAddress((void**)&topk_ptr, g_topk);
    cudaGetSymbolAddress((void**)&M_ptr, g_M);
    cudaGetSymbolAddress((void**)&hq_ptr, g_hq);
    cudaGetSymbolAddress((void**)&qrelu_ptr, g_qrelu);

    const int k2_smem = 85248;
    cudaFuncSetAttribute(k2_sim, cudaFuncAttributeMaxDynamicSharedMemorySize, k2_smem);
    const int k4_smem = 2 * 128 * 36 * 4 + 2 * 32 * 72 * 4;
    cudaFuncSetAttribute(k_tf32, cudaFuncAttributeMaxDynamicSharedMemorySize, k4_smem);

    k1_prep<<<256, 256>>>(qf);                     // idx 0
    k_nop<<<1, 32>>>();                            // idx 1
    k_nop<<<1, 32>>>();                            // idx 2
    k2_sim<<<NBLK, 256, k2_smem>>>(keys);          // idx 3 -> ncu capture slot
    k3_rescore<<<1024, 256>>>(keys);               // idx 4
    k3b_topk<<<256, 512>>>(keys);                  // idx 5
    k_tf32<<<dim3(64, 4, 2), 256, k4_smem>>>(keys, Wm, topk_ptr, nullptr, nullptr, M_ptr,
                                             qrelu_ptr, Wq, bq, bm, hq_ptr);
    k5_final<<<256, 256>>>(keys, Ws, bs, Wc, bc, out);
}

// round 17
// speedup vs baseline: 1.1261x; 1.1261x over previous
#include <cuda_runtime.h>
#include <cuda_bf16.h>
#include <cstdint>

#define EPSF 1e-8f
#define NKEY 100000
#define NBLK 1563   // ceil(100000/64)

#define QSCALE (127.0f / 6.0f)
#define QC2 ((6.0f / 127.0f) * (6.0f / 127.0f))
#define TH_COS 0.12f

// ---------------- scratch (device globals; no allocs allowed) ----------------
__device__ __align__(16) float          g_qrelu[256 * 512];
__device__ __align__(16) char           g_q8[256 * 512];     // int8 queries
__device__ __align__(16) float          g_qn[256];
__device__ __align__(16) int            g_topk[256 * 32];
__device__ __align__(16) float          g_hq[256 * 256];
__device__ __align__(16) float          g_M[8192 * 256];
__device__ __align__(16) int            g_cand_cnt[256];
__device__ __align__(16) int            g_cand_list[256 * 1024];
__device__ __align__(16) float          g_cand_simf[256 * 1024];

#define CP_ASYNC16(dst, src) \
    asm volatile("cp.async.ca.shared.global [%0], [%1], 16;\n" :: "r"(dst), "l"(src))
#define CP_COMMIT() asm volatile("cp.async.commit_group;\n")
#define CP_WAIT0()  asm volatile("cp.async.wait_group 0;\n")
#define CP_WAIT1()  asm volatile("cp.async.wait_group 1;\n")

__device__ __forceinline__ uint32_t smem_u32(const void* p) {
    uint32_t a;
    asm("{ .reg .u64 t; cvta.to.shared.u64 t, %1; cvt.u32.u64 %0, t; }" : "=r"(a) : "l"(p));
    return a;
}

// pack 4 s32 -> 4 saturated s8 bytes (b0=v0..b3=v3)
__device__ __forceinline__ uint32_t pack_s8x4(int v0, int v1, int v2, int v3) {
    uint32_t t1, w;
    asm("cvt.pack.sat.s8.s32.b32 %0, %1, %2, 0;" : "=r"(t1) : "r"(v3), "r"(v2));
    asm("cvt.pack.sat.s8.s32.b32 %0, %1, %2, %3;" : "=r"(w) : "r"(v1), "r"(v0), "r"(t1));
    return w;
}

__device__ __forceinline__ void cand_push(int m, int gn, float v) {
    if (v >= TH_COS) {
        int p = atomicAdd(&g_cand_cnt[m], 1);
        if (p < 1024) g_cand_list[m * 1024 + p] = gn;
    }
}

// ---------------- K1: relu(q), int8 copy, row norms, zero cand counters ----------------
__global__ void k1_prep(const float* __restrict__ qf) {
    const int b = blockIdx.x, t = threadIdx.x;
    __shared__ float red[8];
    float s = 0.f;
#pragma unroll
    for (int i = 0; i < 2; i++) {
        int d = t + i * 256;
        float v = fmaxf(qf[b * 512 + d], 0.f);
        g_qrelu[b * 512 + d] = v;
        int vi = __float2int_rn(v * QSCALE);
        vi = max(-127, min(127, vi));
        g_q8[b * 512 + d] = (char)vi;
        s += v * v;
    }
    for (int o = 16; o; o >>= 1) s += __shfl_xor_sync(0xffffffffu, s, o);
    if ((t & 31) == 0) red[t >> 5] = s;
    __syncthreads();
    if (t == 0) {
        float tot = 0.f;
        for (int i = 0; i < 8; i++) tot += red[i];
        g_qn[b] = sqrtf(tot);
        g_cand_cnt[b] = 0;
    }
}

// ---------------- K2: int8 sim GEMM (mma.sync m16n8k32.s8), pipelined; fused select ------
// (R14-measured version: cp.async A + register-prefetched keys, 117.8 us)
__global__ void __launch_bounds__(256) k2_sim(const float* __restrict__ keys) {
    extern __shared__ __align__(16) char dsm[];
    char* Ab = dsm;                         // 2 stages x 256x80
    char* Bb = dsm + 2 * 256 * 80;          // 2 stages x 64x80
    float* qn_s = (float*)(dsm + 2 * 256 * 80 + 2 * 64 * 80);
    float* kn_s = qn_s + 256;

    const int t = threadIdx.x;
    const int n0 = blockIdx.x * 64;
    qn_s[t] = g_qn[t];

    int acc[4][4][4];
#pragma unroll
    for (int a = 0; a < 4; a++)
#pragma unroll
        for (int b = 0; b < 4; b++)
#pragma unroll
            for (int c = 0; c < 4; c++) acc[a][b][c] = 0;

    float ssq = 0.f;
    const int lane = t & 31, warp = t >> 5;
    const int wm = warp >> 1, wn = warp & 1;
    const int rb = t >> 2, cq = t & 3;      // B: 4 threads/row, 16 floats each
    const bool rowok = (n0 + rb) < NKEY;
    const float* krow = keys + (size_t)(n0 + rb) * 512 + cq * 16;

    const uint32_t a_sm = smem_u32(Ab);

    // --- A chunk0 via cp.async ---
#pragma unroll
    for (int i = 0; i < 4; i++) {
        int r = rb + 64 * i;
        CP_ASYNC16(a_sm + (uint32_t)(r * 80 + cq * 16), (const void*)&g_q8[r * 512 + cq * 16]);
    }
    CP_COMMIT();
    // --- B chunk0 ---
    float4 f[4];
    if (rowok) {
#pragma unroll
        for (int j = 0; j < 4; j++) f[j] = *reinterpret_cast<const float4*>(krow + j * 4);
    } else {
#pragma unroll
        for (int j = 0; j < 4; j++) f[j] = make_float4(0.f, 0.f, 0.f, 0.f);
    }
    {
        uint4 w;
        uint32_t* wp = (uint32_t*)&w;
#pragma unroll
        for (int j = 0; j < 4; j++) {
            float4 q4 = f[j];
            ssq += q4.x * q4.x + q4.y * q4.y + q4.z * q4.z + q4.w * q4.w;
            wp[j] = pack_s8x4(__float2int_rn(q4.x * QSCALE), __float2int_rn(q4.y * QSCALE),
                              __float2int_rn(q4.z * QSCALE), __float2int_rn(q4.w * QSCALE));
        }
        *reinterpret_cast<uint4*>(Bb + rb * 80 + cq * 16) = w;
    }
    CP_WAIT0();
    __syncthreads();

    for (int s = 0; s < 8; s++) {
        const int cur = s & 1, nxt = cur ^ 1;
        const bool hn = s < 7;
        if (hn) {
            const int k0n = (s + 1) * 64;
#pragma unroll
            for (int i = 0; i < 4; i++) {
                int r = rb + 64 * i;
                CP_ASYNC16(a_sm + (uint32_t)(nxt * 20480 + r * 80 + cq * 16),
                           (const void*)&g_q8[r * 512 + k0n + cq * 16]);
            }
            CP_COMMIT();
            if (rowok) {
#pragma unroll
                for (int j = 0; j < 4; j++)
                    f[j] = *reinterpret_cast<const float4*>(krow + k0n + j * 4);
            }
        }

        const uint32_t ab = a_sm + cur * 20480;
        const uint32_t bb = smem_u32(Bb) + cur * 5120;
#pragma unroll
        for (int ks = 0; ks < 2; ks++) {
            const int kb = ks * 32;
            uint32_t af[4][4];
#pragma unroll
            for (int mi = 0; mi < 4; mi++) {
                int row = wm * 64 + mi * 16 + (lane & 15);
                uint32_t addr = ab + (uint32_t)(row * 80 + kb + ((lane >> 4) << 4));
                asm volatile("ldmatrix.sync.aligned.m8n8.x4.shared.b16 {%0,%1,%2,%3}, [%4];"
                             : "=r"(af[mi][0]), "=r"(af[mi][1]), "=r"(af[mi][2]), "=r"(af[mi][3])
                             : "r"(addr));
            }
            uint32_t bfr[4][2];
#pragma unroll
            for (int p = 0; p < 2; p++) {
                int g = lane >> 3, r = lane & 7;
                int nrow = wn * 32 + p * 16 + ((g >> 1) << 3) + r;
                uint32_t addr = bb + (uint32_t)(nrow * 80 + kb + ((g & 1) << 4));
                uint32_t r0, r1, r2, r3;
                asm volatile("ldmatrix.sync.aligned.m8n8.x4.shared.b16 {%0,%1,%2,%3}, [%4];"
                             : "=r"(r0), "=r"(r1), "=r"(r2), "=r"(r3) : "r"(addr));
                bfr[p * 2][0] = r0;     bfr[p * 2][1] = r1;
                bfr[p * 2 + 1][0] = r2; bfr[p * 2 + 1][1] = r3;
            }
#pragma unroll
            for (int mi = 0; mi < 4; mi++)
#pragma unroll
                for (int ni = 0; ni < 4; ni++)
                    asm volatile(
                        "mma.sync.aligned.m16n8k32.row.col.s32.s8.s8.s32 "
                        "{%0,%1,%2,%3}, {%4,%5,%6,%7}, {%8,%9}, {%0,%1,%2,%3};"
                        : "+r"(acc[mi][ni][0]), "+r"(acc[mi][ni][1]),
                          "+r"(acc[mi][ni][2]), "+r"(acc[mi][ni][3])
                        : "r"(af[mi][0]), "r"(af[mi][1]), "r"(af[mi][2]), "r"(af[mi][3]),
                          "r"(bfr[ni][0]), "r"(bfr[ni][1]));
        }

        if (hn) {
            uint4 w;
            uint32_t* wp = (uint32_t*)&w;
#pragma unroll
            for (int j = 0; j < 4; j++) {
                float4 q4 = f[j];
                if (rowok)
                    ssq += q4.x * q4.x + q4.y * q4.y + q4.z * q4.z + q4.w * q4.w;
                wp[j] = rowok ? pack_s8x4(__float2int_rn(q4.x * QSCALE),
                                          __float2int_rn(q4.y * QSCALE),
                                          __float2int_rn(q4.z * QSCALE),
                                          __float2int_rn(q4.w * QSCALE))
                              : 0u;
            }
            *reinterpret_cast<uint4*>(Bb + nxt * 5120 + rb * 80 + cq * 16) = w;
            CP_WAIT0();
        }
        __syncthreads();
    }

    ssq += __shfl_xor_sync(0xffffffffu, ssq, 1);
    ssq += __shfl_xor_sync(0xffffffffu, ssq, 2);
    if (cq == 0) kn_s[rb] = sqrtf(ssq);
    __syncthreads();

    // epilogue: cosine scaling + fused candidate push (no sim-matrix store)
#pragma unroll
    for (int mi = 0; mi < 4; mi++) {
        int m = wm * 64 + mi * 16 + (lane >> 2);
        float qn0 = qn_s[m], qn1 = qn_s[m + 8];
#pragma unroll
        for (int ni = 0; ni < 4; ni++) {
            int nl = wn * 32 + ni * 8 + ((lane & 3) << 1);
            int gn = n0 + nl;
            if (gn < NKEY) {
                float kn0 = kn_s[nl], kn1 = kn_s[nl + 1];
                cand_push(m,     gn,     (float)acc[mi][ni][0] * (QC2 / fmaxf(qn0 * kn0, EPSF)));
                cand_push(m,     gn + 1, (float)acc[mi][ni][1] * (QC2 / fmaxf(qn0 * kn1, EPSF)));
                cand_push(m + 8, gn,     (float)acc[mi][ni][2] * (QC2 / fmaxf(qn1 * kn0, EPSF)));
                cand_push(m + 8, gn + 1, (float)acc[mi][ni][3] * (QC2 / fmaxf(qn1 * kn1, EPSF)));
            }
        }
    }
}

// ---------------- K3a: rescore candidates (4 blocks per query, disjoint strides) ---------
__global__ void __launch_bounds__(256) k3_rescore(const float* __restrict__ keys) {
    const int b = blockIdx.x >> 2, j = blockIdx.x & 3;
    const int t = threadIdx.x;
    __shared__ float q_s[512];
    q_s[t] = g_qrelu[b * 512 + t];
    q_s[t + 256] = g_qrelu[b * 512 + 256 + t];
    __syncthreads();

    const int cnt = g_cand_cnt[b];
    if (cnt < 48 || cnt > 1024) return;          // fallback handled in k3b

    const int lane = t & 31, warp = t >> 5;
    const float qn = g_qn[b];
    for (int c = j * 8 + warp; c < cnt; c += 32) {
        const float* kp = keys + (size_t)g_cand_list[b * 1024 + c] * 512;
        float4 kv[4], qv[4];
#pragma unroll
        for (int i = 0; i < 4; i++) {
            kv[i] = *reinterpret_cast<const float4*>(kp + i * 128 + lane * 4);
            qv[i] = *reinterpret_cast<const float4*>(&q_s[i * 128 + lane * 4]);
        }
        float d0 = 0.f, d1 = 0.f, d2 = 0.f, d3 = 0.f;
        float s0 = 0.f, s1 = 0.f, s2 = 0.f, s3 = 0.f;
#pragma unroll
        for (int i = 0; i < 4; i++) {
            d0 += qv[i].x * kv[i].x;  s0 += kv[i].x * kv[i].x;
            d1 += qv[i].y * kv[i].y;  s1 += kv[i].y * kv[i].y;
            d2 += qv[i].z * kv[i].z;  s2 += kv[i].z * kv[i].z;
            d3 += qv[i].w * kv[i].w;  s3 += kv[i].w * kv[i].w;
        }
        float dot = (d0 + d1) + (d2 + d3);
        float ksq = (s0 + s1) + (s2 + s3);
        for (int o = 16; o; o >>= 1) {
            dot += __shfl_xor_sync(0xffffffffu, dot, o);
            ksq += __shfl_xor_sync(0xffffffffu, ksq, o);
        }
        if (lane == 0)
            g_cand_simf[b * 1024 + c] = dot / fmaxf(qn * sqrtf(ksq), EPSF);
    }
}

// ---------------- K3b: exact top-32 (fast: from rescored list; fallback: exact argmax) ---
__global__ void __launch_bounds__(512) k3b_topk(const float* __restrict__ keys) {
    const int b = blockIdx.x, t = threadIdx.x;
    const int lane = t & 31, warp = t >> 5;
    __shared__ int   cand_idx[1024];
    __shared__ float cand_sim[1024];
    __shared__ float q_s[512];
    __shared__ float wb_v[16];
    __shared__ int   wb_i[16];
    __shared__ int   sel[32];

    const int cnt_raw = g_cand_cnt[b];

    if (cnt_raw >= 48 && cnt_raw <= 1024) {
        const int cnt = cnt_raw;
        for (int i = t; i < cnt; i += 512) {
            cand_idx[i] = g_cand_list[b * 1024 + i];
            cand_sim[i] = g_cand_simf[b * 1024 + i];
        }
        __syncthreads();
        if (warp == 0) {
            for (int r = 0; r < 32; r++) {
                float best = -1e30f; int bkey = 0x7fffffff, bslot = -1;
                for (int c = lane; c < cnt; c += 32) {
                    float v = cand_sim[c]; int ki = cand_idx[c];
                    if (v > best || (v == best && ki < bkey)) { best = v; bkey = ki; bslot = c; }
                }
                for (int o = 16; o; o >>= 1) {
                    float ov = __shfl_xor_sync(0xffffffffu, best, o);
                    int   ok = __shfl_xor_sync(0xffffffffu, bkey, o);
                    int   os = __shfl_xor_sync(0xffffffffu, bslot, o);
                    if (ov > best || (ov == best && ok < bkey)) { best = ov; bkey = ok; bslot = os; }
                }
                if (lane == 0) {
                    g_topk[b * 32 + r] = bkey;
                    cand_sim[bslot] = -2e30f;
                }
                __syncwarp();
            }
        }
        return;
    }

    // ---- robust fallback (dead code for this input distribution): exact 32-pass argmax ----
    q_s[t] = g_qrelu[b * 512 + t];
    __syncthreads();
    const float qn = g_qn[b];
    for (int r = 0; r < 32; r++) {
        float best = -1e30f; int bkey = 0x7fffffff;
        for (int k = warp; k < NKEY; k += 16) {
            bool taken = false;
            for (int u = 0; u < r; u++) taken |= (sel[u] == k);
            if (taken) continue;
            const float* kp = keys + (size_t)k * 512;
            float dot = 0.f, ksq = 0.f;
#pragma unroll
            for (int i = 0; i < 4; i++) {
                float4 kv = *reinterpret_cast<const float4*>(kp + i * 128 + lane * 4);
                float4 qv = *reinterpret_cast<const float4*>(&q_s[i * 128 + lane * 4]);
                dot += qv.x * kv.x + qv.y * kv.y + qv.z * kv.z + qv.w * kv.w;
                ksq += kv.x * kv.x + kv.y * kv.y + kv.z * kv.z + kv.w * kv.w;
            }
            for (int o = 16; o; o >>= 1) {
                dot += __shfl_xor_sync(0xffffffffu, dot, o);
                ksq += __shfl_xor_sync(0xffffffffu, ksq, o);
            }
            float v = dot / fmaxf(qn * sqrtf(ksq), EPSF);
            if (v > best || (v == best && k < bkey)) { best = v; bkey = k; }
        }
        if (lane == 0) { wb_v[warp] = best; wb_i[warp] = bkey; }
        __syncthreads();
        if (t == 0) {
            float bv = -1e30f; int bi = 0x7fffffff;
            for (int w = 0; w < 16; w++) {
                if (wb_v[w] > bv || (wb_v[w] == bv && wb_i[w] < bi)) { bv = wb_v[w]; bi = wb_i[w]; }
            }
            sel[r] = bi;
            g_topk[b * 32 + r] = bi;
        }
        __syncthreads();
    }
}

// ---------------- K4: tf32 GEMM, cp.async double-buffered, dual-task grid ----------------
__global__ void __launch_bounds__(256) k_tf32(const float* __restrict__ A,
                                              const float* __restrict__ W,
                                              const int* __restrict__ idx,
                                              const float* __restrict__ b1,
                                              const float* __restrict__ b2,
                                              float* __restrict__ C,
                                              const float* __restrict__ A2,
                                              const float* __restrict__ W2,
                                              const float* __restrict__ b2a,
                                              const float* __restrict__ b2b,
                                              float* __restrict__ C2) {
    if (blockIdx.z == 1) {
        if (blockIdx.x >= 2) return;     // small task: M=256 -> 2 M-blocks
        A = A2; W = W2; idx = nullptr; b1 = b2a; b2 = b2b; C = C2;
    }
    extern __shared__ __align__(16) char sm2[];
    uint32_t* AsU = (uint32_t*)sm2;                       // 2 stages x 128x36
    uint32_t* BsU = (uint32_t*)(sm2 + 2 * 128 * 36 * 4);  // 2 stages x 32x72
    const uint32_t as32 = smem_u32(AsU);
    const uint32_t bs32 = smem_u32(BsU);

    const int t = threadIdx.x;
    const int lane = t & 31, warp = t >> 5;
    const int wm = (warp >> 1) * 32, wn = (warp & 1) * 32;
    const int m0 = blockIdx.x * 128, n0 = blockIdx.y * 64;

    float acc[2][4][4];
#pragma unroll
    for (int i = 0; i < 2; i++)
#pragma unroll
        for (int j = 0; j < 4; j++)
#pragma unroll
            for (int k = 0; k < 4; k++) acc[i][j][k] = 0.f;

    const int alrow = t >> 1;
    const int acol0 = (t & 1) * 16;
    const float* arow = (idx ? (A + (size_t)idx[m0 + alrow] * 512)
                             : (A + (size_t)(m0 + alrow) * 512)) + acol0;
    const int wr = t >> 3;
    const int wc = (t & 7) * 8;
    const float* wrow = W + (size_t)wr * 256 + n0 + wc;

    // issue stage 0 (k0 = 0)
#pragma unroll
    for (int q = 0; q < 4; q++)
        CP_ASYNC16(as32 + (uint32_t)((alrow * 36 + acol0 + q * 4) * 4),
                   (const void*)(arow + q * 4));
#pragma unroll
    for (int q = 0; q < 2; q++)
        CP_ASYNC16(bs32 + (uint32_t)((wr * 72 + wc + q * 4) * 4),
                   (const void*)(wrow + q * 4));
    CP_COMMIT();

    for (int it = 0; it < 16; it++) {
        const int cur = it & 1, nxt = cur ^ 1;
        const bool hn = it < 15;
        if (hn) {
            const int kn = (it + 1) * 32;
#pragma unroll
            for (int q = 0; q < 4; q++)
                CP_ASYNC16(as32 + (uint32_t)(((nxt * 128 + alrow) * 36 + acol0 + q * 4) * 4),
                           (const void*)(arow + kn + q * 4));
#pragma unroll
            for (int q = 0; q < 2; q++)
                CP_ASYNC16(bs32 + (uint32_t)(((nxt * 32 + wr) * 72 + wc + q * 4) * 4),
                           (const void*)(wrow + (size_t)kn * 256 + q * 4));
            CP_COMMIT();
            CP_WAIT1();
        } else {
            CP_WAIT0();
        }
        __syncthreads();

        const uint32_t* Ac = AsU + cur * 128 * 36;
        const uint32_t* Bc = BsU + cur * 32 * 72;
#pragma unroll
        for (int ks = 0; ks < 4; ks++) {
            const int kc = ks * 8;
            uint32_t a[2][4];
#pragma unroll
            for (int mi = 0; mi < 2; mi++) {
                int r0 = wm + mi * 16 + (lane >> 2);
                a[mi][0] = Ac[r0 * 36 + kc + (lane & 3)];
                a[mi][1] = Ac[(r0 + 8) * 36 + kc + (lane & 3)];
                a[mi][2] = Ac[r0 * 36 + kc + (lane & 3) + 4];
                a[mi][3] = Ac[(r0 + 8) * 36 + kc + (lane & 3) + 4];
            }
            uint32_t bb[4][2];
#pragma unroll
            for (int ni = 0; ni < 4; ni++) {
                int nc = wn + ni * 8 + (lane >> 2);
                bb[ni][0] = Bc[(kc + (lane & 3)) * 72 + nc];
                bb[ni][1] = Bc[(kc + (lane & 3) + 4) * 72 + nc];
            }
#pragma unroll
            for (int mi = 0; mi < 2; mi++)
#pragma unroll
                for (int ni = 0; ni < 4; ni++)
                    asm volatile(
                        "mma.sync.aligned.m16n8k8.row.col.f32.tf32.tf32.f32 "
                        "{%0,%1,%2,%3}, {%4,%5,%6,%7}, {%8,%9}, {%0,%1,%2,%3};"
                        : "+f"(acc[mi][ni][0]), "+f"(acc[mi][ni][1]),
                          "+f"(acc[mi][ni][2]), "+f"(acc[mi][ni][3])
                        : "r"(a[mi][0]), "r"(a[mi][1]), "r"(a[mi][2]), "r"(a[mi][3]),
                          "r"(bb[ni][0]), "r"(bb[ni][1]));
        }
        __syncthreads();
    }

#pragma unroll
    for (int mi = 0; mi < 2; mi++) {
        int r0 = m0 + wm + mi * 16 + (lane >> 2);
#pragma unroll
        for (int ni = 0; ni < 4; ni++) {
            int c0 = n0 + wn + ni * 8 + (lane & 3) * 2;
            float add0 = (b1 ? b1[c0] : 0.f) + (b2 ? b2[c0] : 0.f);
            float add1 = (b1 ? b1[c0 + 1] : 0.f) + (b2 ? b2[c0 + 1] : 0.f);
            C[(size_t)r0 * 256 + c0]           = acc[mi][ni][0] + add0;
            C[(size_t)r0 * 256 + c0 + 1]       = acc[mi][ni][1] + add1;
            C[(size_t)(r0 + 8) * 256 + c0]     = acc[mi][ni][2] + add0;
            C[(size_t)(r0 + 8) * 256 + c0 + 1] = acc[mi][ni][3] + add1;
        }
    }
}

// ---------------- K5: scores -> softmax -> attended -> classifier (coalesced) ------------
__global__ void k5_final(const float* __restrict__ keys, const float* __restrict__ Ws,
                         const float* __restrict__ bs, const float* __restrict__ Wc,
                         const float* __restrict__ bc, float* __restrict__ out) {
    const int b = blockIdx.x, t = threadIdx.x, lane = t & 31, warp = t >> 5;
    __shared__ float hq_s[256], sc_s[32], w_s[32], merged[1024];
    __shared__ float part[8][128];
    __shared__ int idx_s[32];
    hq_s[t] = g_hq[b * 256 + t];
    if (t < 32) idx_s[t] = g_topk[b * 32 + t];
    merged[t] = g_qrelu[b * 512 + t];
    merged[256 + t] = g_qrelu[b * 512 + 256 + t];
    __syncthreads();

    for (int k = warp; k < 32; k += 8) {
        const float* Mrow = &g_M[(size_t)(b * 32 + k) * 256];
        float s = 0.f;
        for (int a = lane; a < 256; a += 32) s += tanhf(hq_s[a] + Mrow[a]) * Ws[a];
        for (int o = 16; o; o >>= 1) s += __shfl_xor_sync(0xffffffffu, s, o);
        if (lane == 0) sc_s[k] = s + bs[0];
    }
    __syncthreads();
    if (t < 32) {
        float v = sc_s[t];
        float m = v;
        for (int o = 16; o; o >>= 1) m = fmaxf(m, __shfl_xor_sync(0xffffffffu, m, o));
        float e = expf(v - m);
        float sm = e;
        for (int o = 16; o; o >>= 1) sm += __shfl_xor_sync(0xffffffffu, sm, o);
        w_s[t] = e / sm;
    }
    __syncthreads();
    for (int d = t; d < 512; d += 256) {
        float a = 0.f;
#pragma unroll 8
        for (int k = 0; k < 32; k++) a += w_s[k] * keys[(size_t)idx_s[k] * 512 + d];
        merged[512 + d] = a;
    }
    __syncthreads();

    // classifier: lanes map to output columns (coalesced Wc reads), warps split j
    {
        float a0 = 0.f, a1 = 0.f, a2 = 0.f, a3 = 0.f;
        const int j0 = warp * 128;
        for (int j = j0; j < j0 + 128; j++) {
            float mv = merged[j];
            const float* wr = Wc + (size_t)j * 100;
            a0 += mv * wr[lane];
            a1 += mv * wr[lane + 32];
            a2 += mv * wr[lane + 64];
            if (lane < 4) a3 += mv * wr[lane + 96];
        }
        part[warp][lane] = a0;
        part[warp][lane + 32] = a1;
        part[warp][lane + 64] = a2;
        if (lane < 4) part[warp][lane + 96] = a3;
    }
    __syncthreads();
    if (t < 100) {
        float s = bc[t];
#pragma unroll
        for (int w = 0; w < 8; w++) s += part[w][t];
        out[b * 100 + t] = s;
    }
}

// ---------------- launch ----------------
extern "C" void kernel_launch(void* const* d_in, const int* in_sizes, int n_in,
                              void* d_out, int out_size) {
    const float* qf   = (const float*)d_in[0];
    const float* keys = (const float*)d_in[1];
    const float* Wq   = (const float*)d_in[2];
    const float* bq   = (const float*)d_in[3];
    const float* Wm   = (const float*)d_in[4];
    const float* bm   = (const float*)d_in[5];
    const float* Ws   = (const float*)d_in[6];
    const float* bs   = (const float*)d_in[7];
    const float* Wc   = (const float*)d_in[8];
    const float* bc   = (const float*)d_in[9];
    float* out = (float*)d_out;

    int* topk_ptr = nullptr;
    float* M_ptr = nullptr; float* hq_ptr = nullptr; float* qrelu_ptr = nullptr;
    cudaGetSymbolAddress((void**)&topk_ptr, g_topk);
    cudaGetSymbolAddress((void**)&M_ptr, g_M);
    cudaGetSymbolAddress((void**)&hq_ptr, g_hq);
    cudaGetSymbolAddress((void**)&qrelu_ptr, g_qrelu);

    const int k2_smem = 2 * 256 * 80 + 2 * 64 * 80 + (256 + 64) * 4;
    cudaFuncSetAttribute(k2_sim, cudaFuncAttributeMaxDynamicSharedMemorySize, k2_smem);
    const int k4_smem = 2 * 128 * 36 * 4 + 2 * 32 * 72 * 4;
    cudaFuncSetAttribute(k_tf32, cudaFuncAttributeMaxDynamicSharedMemorySize, k4_smem);

    k1_prep<<<256, 256>>>(qf);                     // idx 0
    k2_sim<<<NBLK, 256, k2_smem>>>(keys);          // idx 1
    k3_rescore<<<1024, 256>>>(keys);               // idx 2
    k3b_topk<<<256, 512>>>(keys);                  // idx 3 -> ncu capture slot
    k_tf32<<<dim3(64, 4, 2), 256, k4_smem>>>(keys, Wm, topk_ptr, nullptr, nullptr, M_ptr,
                                             qrelu_ptr, Wq, bq, bm, hq_ptr);
    k5_final<<<256, 256>>>(keys, Ws, bs, Wc, bc, out);
}